// round 14
// baseline (speedup 1.0000x reference)
#include <cuda_runtime.h>
#include <cuda_bf16.h>
#include <math.h>
#include <cstdint>

#define NN   64      // batch
#define TDEC 100     // decoder text length
#define TS   99      // decode steps (T_DEC-1)
#define HD   512     // hidden dim (LSTM1)
#define KSZ  128     // key size (LSTM2 hidden)
#define VSZ  128     // value size
#define G1   2048    // 4*HD
#define G2   512     // 4*KSZ
#define TEN  512     // encoder length
#define VOC  32000
#define NROW (TS * NN)   // 6336 output rows
#define KOUT 256         // projection K
#define K1   640         // LSTM1 recurrent K (ctx 128 + h1 512)
#define NBLK 128     // persistent loop grid

// ---------------- persistent device scratch ----------------
__device__ float g_pre1[(size_t)TS * NN * G1];
__device__ float g_h1[NN * HD], g_c1[NN * HD];
__device__ float g_h2[NN * KSZ], g_c2[NN * KSZ];
__device__ float g_ctx[NN * VSZ];
__device__ float g_partA[4 * NN * G1];              // LSTM1 k-split partials
__device__ float g_partC[16 * NN * G2];             // LSTM2 k-split partials
__device__ __nv_bfloat16 g_W1hi[(size_t)G1 * K1];   // [ctx|h1] recurrent weight hi/lo
__device__ __nv_bfloat16 g_W1lo[(size_t)G1 * K1];
__device__ __nv_bfloat16 g_W1ehi[(size_t)G1 * HD];  // emb-part weight hi/lo
__device__ __nv_bfloat16 g_W1elo[(size_t)G1 * HD];
__device__ __nv_bfloat16 g_Ehi[(size_t)VOC * HD];   // embedding table hi/lo
__device__ __nv_bfloat16 g_Elo[(size_t)VOC * HD];
__device__ __nv_bfloat16 g_Whi[(size_t)VOC * KOUT];
__device__ __nv_bfloat16 g_Wlo[(size_t)VOC * KOUT];
__device__ __nv_bfloat16 g_Xhi[(size_t)NROW * KOUT];
__device__ __nv_bfloat16 g_Xlo[(size_t)NROW * KOUT];

__device__ unsigned g_bar_count;
__device__ volatile unsigned g_bar_gen;

__device__ __forceinline__ float sigf(float x) { return 1.0f / (1.0f + expf(-x)); }

__device__ __forceinline__ uint32_t smem_u32(const void* p) {
    uint32_t a;
    asm("{ .reg .u64 t; cvta.to.shared.u64 t, %1; cvt.u32.u64 %0, t; }" : "=r"(a) : "l"(p));
    return a;
}
__device__ __forceinline__ void ldsm_x4(uint32_t* r, uint32_t addr) {
    asm volatile("ldmatrix.sync.aligned.m8n8.x4.shared.b16 {%0,%1,%2,%3}, [%4];"
                 : "=r"(r[0]), "=r"(r[1]), "=r"(r[2]), "=r"(r[3]) : "r"(addr));
}
__device__ __forceinline__ void mma_bf16(float* d, const uint32_t* a, const uint32_t* b) {
    asm volatile("mma.sync.aligned.m16n8k16.row.col.f32.bf16.bf16.f32 "
        "{%0,%1,%2,%3}, {%4,%5,%6,%7}, {%8,%9}, {%0,%1,%2,%3};"
        : "+f"(d[0]), "+f"(d[1]), "+f"(d[2]), "+f"(d[3])
        : "r"(a[0]), "r"(a[1]), "r"(a[2]), "r"(a[3]), "r"(b[0]), "r"(b[1]));
}
__device__ __forceinline__ void cp_async16(uint32_t dst, const void* src, bool pred) {
    int sz = pred ? 16 : 0;
    asm volatile("cp.async.cg.shared.global [%0], [%1], 16, %2;"
                 :: "r"(dst), "l"(src), "r"(sz) : "memory");
}
#define CP_COMMIT() asm volatile("cp.async.commit_group;" ::: "memory")
#define CP_WAIT(n)  asm volatile("cp.async.wait_group %0;" :: "n"(n) : "memory")

// swizzled SMEM offset within a [rows x 64B] bf16 k32 tile (ldmatrix conflict-free)
__device__ __forceinline__ uint32_t swz(int row, int c16) {
    return (uint32_t)(row * 64 + ((c16 ^ ((row >> 1) & 3)) << 4));
}

// ---------------- init ----------------
__global__ void init_kernel() {
    int i = blockIdx.x * blockDim.x + threadIdx.x;
    if (i == 0) { g_bar_count = 0; g_bar_gen = 0; }
    if (i < NN * HD)  { g_h1[i] = 0.f; g_c1[i] = 0.f; }
    if (i < NN * KSZ) { g_h2[i] = 0.f; g_c2[i] = 0.f; g_ctx[i] = 0.f; }
}

// ---------------- conversions ----------------
__global__ void convW_kernel(const float* __restrict__ Wout) {
    size_t i = (size_t)blockIdx.x * 256 + threadIdx.x;
    float w = Wout[i];
    __nv_bfloat16 hi = __float2bfloat16(w);
    g_Whi[i] = hi;
    g_Wlo[i] = __float2bfloat16(w - __bfloat162float(hi));
}
__global__ void convW1_kernel(const float* __restrict__ Wih1, const float* __restrict__ Whh1) {
    size_t i = (size_t)blockIdx.x * 256 + threadIdx.x;   // G1*K1
    int col = (int)(i / K1), k = (int)(i % K1);
    float w = (k < 128) ? Wih1[(size_t)col * 640 + 512 + k] : Whh1[(size_t)col * 512 + k - 128];
    __nv_bfloat16 hi = __float2bfloat16(w);
    g_W1hi[i] = hi;
    g_W1lo[i] = __float2bfloat16(w - __bfloat162float(hi));
}
__global__ void convWe_kernel(const float* __restrict__ Wih1) {
    size_t i = (size_t)blockIdx.x * 256 + threadIdx.x;   // G1*HD
    int col = (int)(i / HD), k = (int)(i % HD);
    float w = Wih1[(size_t)col * 640 + k];
    __nv_bfloat16 hi = __float2bfloat16(w);
    g_W1ehi[i] = hi;
    g_W1elo[i] = __float2bfloat16(w - __bfloat162float(hi));
}
__global__ void convE_kernel(const float* __restrict__ emb) {
    size_t i = (size_t)blockIdx.x * 256 + threadIdx.x;   // VOC*HD
    float w = emb[i];
    __nv_bfloat16 hi = __float2bfloat16(w);
    g_Ehi[i] = hi;
    g_Elo[i] = __float2bfloat16(w - __bfloat162float(hi));
}

// ============================================================================
// pre1 via warp MMA (unchanged from R9)
// ============================================================================
#define TILE_B 8192
#define STAGE_B (4 * TILE_B)
#define PRE_SMEM (2 * STAGE_B)

__global__ __launch_bounds__(256) void pre1_mma(
    const int* __restrict__ text,
    const float* __restrict__ bih1, const float* __restrict__ bhh1)
{
    extern __shared__ __align__(16) uint8_t sm[];
    uint32_t sbase = smem_u32(sm);

    int cb = blockIdx.x * 128;
    int mb = blockIdx.y * 128;
    int tx = threadIdx.x, wid = tx >> 5, lane = tx & 31;
    int wr = wid >> 2, wcid = wid & 3;

    float acc[4][4][4];
#pragma unroll
    for (int a = 0; a < 4; a++)
#pragma unroll
        for (int b = 0; b < 4; b++)
#pragma unroll
            for (int c = 0; c < 4; c++) acc[a][b][c] = 0.f;

    int lrow = tx >> 1;
    int cpair = (tx & 1) * 2;
    int gr0 = mb + lrow;
    bool xok = gr0 < NROW;
    int tok = 0;
    if (xok) {
        int tt = gr0 >> 6, nn = gr0 & 63;
        tok = text[nn * TDEC + tt];
    }
    const uint8_t* gXhi = (const uint8_t*)(g_Ehi + (size_t)tok * HD);
    const uint8_t* gXlo = (const uint8_t*)(g_Elo + (size_t)tok * HD);
    const uint8_t* gWhi = (const uint8_t*)(g_W1ehi + (size_t)(cb + lrow) * HD);
    const uint8_t* gWlo = (const uint8_t*)(g_W1elo + (size_t)(cb + lrow) * HD);

    int rA = (lane & 7) + ((lane & 8) ? 8 : 0);
    int cAq = lane >> 4;
    int rB = (lane & 7) + ((lane & 16) ? 8 : 0);
    int cBq = (lane >> 3) & 1;

    auto load_stage = [&](int kc, int stg) {
        uint32_t st = sbase + stg * STAGE_B;
        int kb = kc * 64;
#pragma unroll
        for (int q = 0; q < 2; q++) {
            int c = cpair + q;
            uint32_t so = swz(lrow, c);
            int go = kb + c * 16;
            cp_async16(st + so,              gXhi + go, xok);
            cp_async16(st + TILE_B + so,     gXlo + go, xok);
            cp_async16(st + 2 * TILE_B + so, gWhi + go, true);
            cp_async16(st + 3 * TILE_B + so, gWlo + go, true);
        }
        CP_COMMIT();
    };

    load_stage(0, 0);

    for (int kc = 0; kc < 16; kc++) {
        int stg = kc & 1;
        if (kc + 1 < 16) {
            load_stage(kc + 1, stg ^ 1);
            CP_WAIT(1);
        } else {
            CP_WAIT(0);
        }
        __syncthreads();

        uint32_t pXhi = sbase + stg * STAGE_B;
        uint32_t pXlo = pXhi + TILE_B;
        uint32_t pWhi = pXhi + 2 * TILE_B;
        uint32_t pWlo = pXhi + 3 * TILE_B;

#pragma unroll
        for (int ks = 0; ks < 2; ks++) {
            int c0 = ks * 2;
            uint32_t bh[8], bl[8];
#pragma unroll
            for (int pr = 0; pr < 2; pr++) {
                int n0 = wcid * 32 + pr * 16;
                ldsm_x4(bh + pr * 4, pWhi + swz(n0 + rB, c0 + cBq));
                ldsm_x4(bl + pr * 4, pWlo + swz(n0 + rB, c0 + cBq));
            }
#pragma unroll
            for (int mt = 0; mt < 4; mt++) {
                int m0 = wr * 64 + mt * 16;
                uint32_t ah[4], al[4];
                ldsm_x4(ah, pXhi + swz(m0 + rA, c0 + cAq));
                ldsm_x4(al, pXlo + swz(m0 + rA, c0 + cAq));
#pragma unroll
                for (int nt = 0; nt < 4; nt++) {
                    mma_bf16(acc[mt][nt], ah, &bh[nt * 2]);
                    mma_bf16(acc[mt][nt], ah, &bl[nt * 2]);
                    mma_bf16(acc[mt][nt], al, &bh[nt * 2]);
                }
            }
        }
        __syncthreads();
    }

    int g = lane >> 2, tg = lane & 3;
#pragma unroll
    for (int mt = 0; mt < 4; mt++) {
        int r0 = mb + wr * 64 + mt * 16 + g;
#pragma unroll
        for (int half = 0; half < 2; half++) {
            int gr = r0 + half * 8;
            if (gr >= NROW) continue;
            float* prow = g_pre1 + (size_t)gr * G1;
#pragma unroll
            for (int nt = 0; nt < 4; nt++) {
                int c = cb + wcid * 32 + nt * 8 + 2 * tg;
                float2 o;
                o.x = acc[mt][nt][half * 2 + 0] + bih1[c] + bhh1[c];
                o.y = acc[mt][nt][half * 2 + 1] + bih1[c + 1] + bhh1[c + 1];
                *(float2*)(prow + c) = o;
            }
        }
    }
}

// ============================================================================
// Persistent recurrence (exact R9 version — known 4222us config)
// ============================================================================
#define AW_HI 0
#define AW_LO 20480
#define AX_HI 40960
#define AX_LO 61440
#define A_SMEM 81920

__device__ __forceinline__ void gbar(unsigned* gen) {
    __syncthreads();
    if (threadIdx.x == 0) {
        unsigned g = ++(*gen);
        __threadfence();
        unsigned arr = atomicAdd(&g_bar_count, 1u) + 1u;
        if (arr == g * NBLK) {
            g_bar_gen = g;
        } else {
            while (g_bar_gen < g) __nanosleep(64);
        }
        __threadfence();
    }
    __syncthreads();
}

__global__ __launch_bounds__(512) void loop_kernel(
    const float* __restrict__ enc_key, const float* __restrict__ values,
    const int* __restrict__ lens,
    const float* __restrict__ Wih2, const float* __restrict__ Whh2,
    const float* __restrict__ bih2, const float* __restrict__ bhh2,
    float* __restrict__ out_attn)
{
    extern __shared__ __align__(16) uint8_t dsm[];
    uint32_t sA = smem_u32(dsm);

    int bid = blockIdx.x;
    int tx = threadIdx.x;
    int lane = tx & 31, warp = tx >> 5;
    unsigned gen = 0;

    __shared__ float sXC[64][9];
    __shared__ float sWC[8][64];
    __shared__ __align__(16) float sh2[128];
    __shared__ float se[512];
    __shared__ float sbuf[512];
    __shared__ float swred[32];

    int acg = bid >> 2;
    int aky = bid & 3;
    int wr   = warp >> 2;
    int wcid = warp & 3;
    int rA = (lane & 7) + ((lane & 8) ? 8 : 0);
    int cAq = lane >> 4;
    int rB = (lane & 7) + ((lane & 16) ? 8 : 0);
    int cBq = (lane >> 3) & 1;

    int ccg = bid & 7;
    int cky = bid >> 3;
    int cxrow = tx >> 3;
    int cxk   = tx & 7;
    int cwk   = tx >> 6;
    int cwc   = tx & 63;
    int grWC = (cwc >> 4) * 128 + ccg * 16 + (cwc & 15);
    const float* wihC = Wih2 + (size_t)grWC * 512;
    const float* whhC = Whh2 + (size_t)grWC * 128;

    int lenD = (bid < NN) ? lens[bid] : 0;

    // preload resident W1 slice (64 cols x 160 k, hi+lo)
    for (int i = tx; i < 64 * 5 * 4; i += 512) {
        int r = i / 20, rem = i % 20, kc = rem >> 2, c16 = rem & 3;
        size_t go = (size_t)(acg * 64 + r) * K1 + aky * 160 + kc * 32 + c16 * 8;
        uint32_t so = (uint32_t)(kc * 4096) + swz(r, c16);
        *(uint4*)(dsm + AW_HI + so) = *(const uint4*)(g_W1hi + go);
        *(uint4*)(dsm + AW_LO + so) = *(const uint4*)(g_W1lo + go);
    }
    __syncthreads();

    for (int t = 0; t < TS; t++) {
        // Phase A: HMMA
        {
            for (int i = tx; i < 64 * 160; i += 512) {
                int r = i / 160, kl = i % 160;
                int kg = aky * 160 + kl;
                float v = (kg < 128) ? __ldcg(&g_ctx[r * VSZ + kg])
                                     : __ldcg(&g_h1[r * HD + kg - 128]);
                __nv_bfloat16 hi = __float2bfloat16(v);
                __nv_bfloat16 lo = __float2bfloat16(v - __bfloat162float(hi));
                uint32_t off = (uint32_t)((kl >> 5) * 4096) + swz(r, (kl & 31) >> 3) + (kl & 7) * 2;
                *(__nv_bfloat16*)(dsm + AX_HI + off) = hi;
                *(__nv_bfloat16*)(dsm + AX_LO + off) = lo;
            }
            __syncthreads();

            float acc2[2][4];
#pragma unroll
            for (int a = 0; a < 2; a++)
#pragma unroll
                for (int c = 0; c < 4; c++) acc2[a][c] = 0.f;

#pragma unroll
            for (int kc = 0; kc < 5; kc++) {
                uint32_t tW = sA + kc * 4096;
                uint32_t tX = sA + AX_HI + kc * 4096;
#pragma unroll
                for (int ks = 0; ks < 2; ks++) {
                    int c0 = ks * 2;
                    uint32_t bh[4], bl[4], ah[4], al[4];
                    ldsm_x4(bh, tW + AW_HI + swz(wcid * 16 + rB, c0 + cBq));
                    ldsm_x4(bl, tW + AW_LO + swz(wcid * 16 + rB, c0 + cBq));
                    ldsm_x4(ah, tX + swz(wr * 16 + rA, c0 + cAq));
                    ldsm_x4(al, tX + (AX_LO - AX_HI) + swz(wr * 16 + rA, c0 + cAq));
#pragma unroll
                    for (int nt = 0; nt < 2; nt++) {
                        mma_bf16(acc2[nt], ah, &bh[nt * 2]);
                        mma_bf16(acc2[nt], ah, &bl[nt * 2]);
                        mma_bf16(acc2[nt], al, &bh[nt * 2]);
                    }
                }
            }
            int g = lane >> 2, tg = lane & 3;
#pragma unroll
            for (int half = 0; half < 2; half++) {
                int n = wr * 16 + g + half * 8;
#pragma unroll
                for (int nt = 0; nt < 2; nt++) {
                    int gcol = acg * 64 + wcid * 16 + nt * 8 + 2 * tg;
                    float2 o;
                    o.x = acc2[nt][half * 2 + 0];
                    o.y = acc2[nt][half * 2 + 1];
                    *(float2*)&g_partA[((size_t)aky * NN + n) * G1 + gcol] = o;
                }
            }
        }
        gbar(&gen);

        // Phase B
        if (bid < 64) {
            int idx = bid * 512 + tx;
            int n = idx >> 9, k = idx & 511;
            const float* gp = g_pre1 + ((size_t)t * NN + n) * G1;
            float gi = gp[k], gf = gp[512 + k], gg = gp[1024 + k], go = gp[1536 + k];
#pragma unroll
            for (int ky = 0; ky < 4; ky++) {
                const float* pp = g_partA + ((size_t)ky * NN + n) * G1;
                gi += __ldcg(pp + k);
                gf += __ldcg(pp + 512 + k);
                gg += __ldcg(pp + 1024 + k);
                go += __ldcg(pp + 1536 + k);
            }
            float c = sigf(gf) * g_c1[idx] + sigf(gi) * tanhf(gg);
            g_c1[idx] = c;
            __stcg(&g_h1[idx], sigf(go) * tanhf(c));
        }
        gbar(&gen);

        // Phase C
        {
            float acc[4][2];
#pragma unroll
            for (int i = 0; i < 4; i++) { acc[i][0] = 0.f; acc[i][1] = 0.f; }

            for (int k0 = 0; k0 < 40; k0 += 8) {
                int kbase = cky * 40 + k0;
                {
                    int kg = kbase + cxk;
                    sXC[cxrow][cxk] = (kg < 512) ? __ldcg(&g_h1[cxrow * HD + kg])
                                                 : __ldcg(&g_h2[cxrow * KSZ + kg - 512]);
                    int kg2 = kbase + cwk;
                    sWC[cwk][cwc] = (kg2 < 512) ? wihC[kg2] : whhC[kg2 - 512];
                }
                __syncthreads();
#pragma unroll
                for (int kk = 0; kk < 8; kk++) {
                    float wv0 = sWC[kk][lane & 31];
                    float wv1 = sWC[kk][(lane & 31) + 32];
#pragma unroll
                    for (int i = 0; i < 4; i++) {
                        float xv = sXC[warp * 4 + i][kk];
                        acc[i][0] += xv * wv0;
                        acc[i][1] += xv * wv1;
                    }
                }
                __syncthreads();
            }
#pragma unroll
            for (int j = 0; j < 2; j++) {
                int cc = lane + 32 * j;
                int gcol = (cc >> 4) * 128 + ccg * 16 + (cc & 15);
#pragma unroll
                for (int i = 0; i < 4; i++) {
                    int n = warp * 4 + i;
                    g_partC[((size_t)cky * NN + n) * G2 + gcol] = acc[i][j];
                }
            }
        }
        gbar(&gen);

        // Phase D
        if (bid < NN) {
            int n = bid;
            {
                float v = bih2[tx] + bhh2[tx];
#pragma unroll
                for (int ky = 0; ky < 16; ky++)
                    v += __ldcg(&g_partC[((size_t)ky * NN + n) * G2 + tx]);
                sbuf[tx] = v;
            }
            __syncthreads();
            if (tx < 128) {
                float gi = sbuf[tx], gf = sbuf[128 + tx], gg = sbuf[256 + tx], go = sbuf[384 + tx];
                float c = sigf(gf) * g_c2[n * KSZ + tx] + sigf(gi) * tanhf(gg);
                g_c2[n * KSZ + tx] = c;
                float h = sigf(go) * tanhf(c);
                __stcg(&g_h2[n * KSZ + tx], h);
                sh2[tx] = h;
                size_t xr = ((size_t)t * NN + n) * KOUT + tx;
                __nv_bfloat16 hi = __float2bfloat16(h);
                g_Xhi[xr] = hi;
                g_Xlo[xr] = __float2bfloat16(h - __bfloat162float(hi));
            }
            __syncthreads();

            float e;
            {
                const float4* er = (const float4*)(enc_key + ((size_t)n * TEN + tx) * KSZ);
                const float4* h4 = (const float4*)sh2;
                e = 0.f;
#pragma unroll
                for (int q = 0; q < 32; q++) {
                    float4 a = er[q], b = h4[q];
                    e += a.x * b.x + a.y * b.y + a.z * b.z + a.w * b.w;
                }
            }
            float m = e;
#pragma unroll
            for (int s = 16; s > 0; s >>= 1) m = fmaxf(m, __shfl_xor_sync(0xffffffffu, m, s));
            if (lane == 0) swred[warp] = m;
            __syncthreads();
            if (tx < 32) {
                float mm = (tx < 16) ? swred[tx] : -1e30f;
#pragma unroll
                for (int s = 8; s > 0; s >>= 1) mm = fmaxf(mm, __shfl_xor_sync(0xffffffffu, mm, s));
                if (tx == 0) swred[0] = mm;
            }
            __syncthreads();
            float M = swred[0];

            float p = (tx < lenD) ? expf(e - M) : 0.f;
            float sum = p;
#pragma unroll
            for (int s = 16; s > 0; s >>= 1) sum += __shfl_xor_sync(0xffffffffu, sum, s);
            __syncthreads();
            if (lane == 0) swred[warp] = sum;
            __syncthreads();
            if (tx < 32) {
                float ss = (tx < 16) ? swred[tx] : 0.f;
#pragma unroll
                for (int s = 8; s > 0; s >>= 1) ss += __shfl_xor_sync(0xffffffffu, ss, s);
                if (tx == 0) swred[0] = ss;
            }
            __syncthreads();
            float a = p * (1.f / swred[0]);
            se[tx] = a;
            out_attn[((size_t)n * TS + t) * TEN + tx] = a;
            __syncthreads();

            int v = tx & 127, qq = tx >> 7;
            float accv = 0.f;
            const float* vb = values + ((size_t)n * TEN + qq * 128) * VSZ + v;
#pragma unroll 8
            for (int it = 0; it < 128; it++) accv += se[qq * 128 + it] * vb[it * VSZ];
            sbuf[tx] = accv;
            __syncthreads();
            if (tx < 128) {
                float cv = sbuf[tx] + sbuf[128 + tx] + sbuf[256 + tx] + sbuf[384 + tx];
                __stcg(&g_ctx[n * VSZ + tx], cv);
                size_t xr = ((size_t)t * NN + n) * KOUT + 128 + tx;
                __nv_bfloat16 hi = __float2bfloat16(cv);
                g_Xhi[xr] = hi;
                g_Xlo[xr] = __float2bfloat16(cv - __bfloat162float(hi));
            }
        }
        gbar(&gen);
    }
}

// ============================================================================
// Output projection via warp MMA: 128 rows x 256 cols per CTA.
// Stage: Xhi 8K | Xlo 8K | Whi 16K | Wlo 16K = 48KB; 2 stages = 96KB.
// ============================================================================
#define OXHI 0
#define OXLO 8192
#define OWHI 16384
#define OWLO 32768
#define OSTAGE 49152
#define OUT_SMEM (2 * OSTAGE)

__global__ __launch_bounds__(256) void out_gemm_mma(
    const float* __restrict__ bout, float* __restrict__ pred)
{
    extern __shared__ __align__(16) uint8_t sm[];
    uint32_t sbase = smem_u32(sm);

    int cb = blockIdx.x * 256;
    int mb = blockIdx.y * 128;
    int tx = threadIdx.x, wid = tx >> 5, lane = tx & 31;
    int wr = wid >> 2, wcid = wid & 3;    // wr: 64-row half; wcid: 64-col group

    float acc[4][8][4];
#pragma unroll
    for (int a = 0; a < 4; a++)
#pragma unroll
        for (int b = 0; b < 8; b++)
#pragma unroll
            for (int c = 0; c < 4; c++) acc[a][b][c] = 0.f;

    // X loader: row=tx>>1, 2 c16 each
    int lrow = tx >> 1;
    int cpair = (tx & 1) * 2;
    bool xok = (mb + lrow) < NROW;
    const uint8_t* gXhi = (const uint8_t*)(g_Xhi + (size_t)(mb + lrow) * KOUT);
    const uint8_t* gXlo = (const uint8_t*)(g_Xlo + (size_t)(mb + lrow) * KOUT);
    // W loader: row=tx (256 rows), 4 c16 each
    const uint8_t* gWhi = (const uint8_t*)(g_Whi + (size_t)(cb + tx) * KOUT);
    const uint8_t* gWlo = (const uint8_t*)(g_Wlo + (size_t)(cb + tx) * KOUT);

    int rA = (lane & 7) + ((lane & 8) ? 8 : 0);
    int cAq = lane >> 4;
    int rB = (lane & 7) + ((lane & 16) ? 8 : 0);
    int cBq = (lane >> 3) & 1;

    auto load_stage = [&](int kc, int stg) {
        uint32_t st = sbase + stg * OSTAGE;
        int kb = kc * 64;
#pragma unroll
        for (int q = 0; q < 2; q++) {
            int c = cpair + q;
            uint32_t so = swz(lrow, c);
            int go = kb + c * 16;
            cp_async16(st + OXHI + so, gXhi + go, xok);
            cp_async16(st + OXLO + so, gXlo + go, xok);
        }
#pragma unroll
        for (int c = 0; c < 4; c++) {
            uint32_t so = swz(tx, c);
            int go = kb + c * 16;
            cp_async16(st + OWHI + so, gWhi + go, true);
            cp_async16(st + OWLO + so, gWlo + go, true);
        }
        CP_COMMIT();
    };

    load_stage(0, 0);

    for (int kc = 0; kc < 8; kc++) {
        int stg = kc & 1;
        if (kc + 1 < 8) {
            load_stage(kc + 1, stg ^ 1);
            CP_WAIT(1);
        } else {
            CP_WAIT(0);
        }
        __syncthreads();

        uint32_t pXhi = sbase + stg * OSTAGE + OXHI;
        uint32_t pXlo = sbase + stg * OSTAGE + OXLO;
        uint32_t pWhi = sbase + stg * OSTAGE + OWHI;
        uint32_t pWlo = sbase + stg * OSTAGE + OWLO;

#pragma unroll
        for (int ks = 0; ks < 2; ks++) {
            int c0 = ks * 2;
            uint32_t bh[16], bl[16];
#pragma unroll
            for (int pr = 0; pr < 4; pr++) {
                int n0 = wcid * 64 + pr * 16;
                ldsm_x4(bh + pr * 4, pWhi + swz(n0 + rB, c0 + cBq));
                ldsm_x4(bl + pr * 4, pWlo + swz(n0 + rB, c0 + cBq));
            }
#pragma unroll
            for (int mt = 0; mt < 4; mt++) {
                int m0 = wr * 64 + mt * 16;
                uint32_t ah[4], al[4];
                ldsm_x4(ah, pXhi + swz(m0 + rA, c0 + cAq));
                ldsm_x4(al, pXlo + swz(m0 + rA, c0 + cAq));
#pragma unroll
                for (int nt = 0; nt < 8; nt++) {
                    mma_bf16(acc[mt][nt], ah, &bh[nt * 2]);
                    mma_bf16(acc[mt][nt], ah, &bl[nt * 2]);
                    mma_bf16(acc[mt][nt], al, &bh[nt * 2]);
                }
            }
        }
        __syncthreads();
    }

    int g = lane >> 2, tg = lane & 3;
#pragma unroll
    for (int mt = 0; mt < 4; mt++) {
        int r0 = mb + wr * 64 + mt * 16 + g;
#pragma unroll
        for (int half = 0; half < 2; half++) {
            int gr = r0 + half * 8;
            if (gr >= NROW) continue;
            int t = gr >> 6, n = gr & 63;
            float* prow = pred + (size_t)n * ((size_t)TS * VOC) + (size_t)t * VOC;
#pragma unroll
            for (int nt = 0; nt < 8; nt++) {
                int c = cb + wcid * 64 + nt * 8 + 2 * tg;
                float2 o;
                o.x = acc[mt][nt][half * 2 + 0] + bout[c];
                o.y = acc[mt][nt][half * 2 + 1] + bout[c + 1];
                *(float2*)(prow + c) = o;
            }
        }
    }
}

// ---------------- launch ----------------
extern "C" void kernel_launch(void* const* d_in, const int* in_sizes, int n_in,
                              void* d_out, int out_size)
{
    const float* enc_key = (const float*)d_in[0];
    const float* values  = (const float*)d_in[1];
    const int*   lens    = (const int*)d_in[2];
    const int*   text    = (const int*)d_in[3];
    const float* emb     = (const float*)d_in[4];
    const float* Wih1    = (const float*)d_in[5];
    const float* Whh1    = (const float*)d_in[6];
    const float* bih1    = (const float*)d_in[7];
    const float* bhh1    = (const float*)d_in[8];
    const float* Wih2    = (const float*)d_in[9];
    const float* Whh2    = (const float*)d_in[10];
    const float* bih2    = (const float*)d_in[11];
    const float* bhh2    = (const float*)d_in[12];
    const float* Wout    = (const float*)d_in[13];
    const float* bout    = (const float*)d_in[14];

    float* pred = (float*)d_out;
    float* attn = (float*)d_out + (size_t)NN * TS * VOC;

    cudaFuncSetAttribute(out_gemm_mma, cudaFuncAttributeMaxDynamicSharedMemorySize, OUT_SMEM);
    cudaFuncSetAttribute(pre1_mma, cudaFuncAttributeMaxDynamicSharedMemorySize, PRE_SMEM);
    cudaFuncSetAttribute(loop_kernel, cudaFuncAttributeMaxDynamicSharedMemorySize, A_SMEM);

    init_kernel<<<128, 256>>>();
    convW_kernel<<<VOC, 256>>>(Wout);
    convW1_kernel<<<(G1 * K1) / 256, 256>>>(Wih1, Whh1);
    convWe_kernel<<<(G1 * HD) / 256, 256>>>(Wih1);
    convE_kernel<<<(VOC * HD) / 256, 256>>>(emb);
    pre1_mma<<<dim3(16, 50), 256, PRE_SMEM>>>(text, bih1, bhh1);
    loop_kernel<<<NBLK, 512, A_SMEM>>>(enc_key, values, lens,
                                       Wih2, Whh2, bih2, bhh2, attn);
    out_gemm_mma<<<dim3(125, 50), 256, OUT_SMEM>>>(bout, pred);
}

// round 17
// speedup vs baseline: 1.6215x; 1.6215x over previous
#include <cuda_runtime.h>
#include <cuda_bf16.h>
#include <math.h>
#include <cstdint>

#define NN   64      // batch
#define TDEC 100     // decoder text length
#define TS   99      // decode steps (T_DEC-1)
#define HD   512     // hidden dim (LSTM1)
#define KSZ  128     // key size (LSTM2 hidden)
#define VSZ  128     // value size
#define G1   2048    // 4*HD
#define G2   512     // 4*KSZ
#define TEN  512     // encoder length
#define VOC  32000
#define NROW (TS * NN)   // 6336 output rows
#define KOUT 256         // projection K
#define K1   640         // LSTM1 recurrent K (ctx 128 + h1 512)
#define NBLK 128     // persistent loop grid

// ---------------- persistent device scratch ----------------
__device__ float g_pre1[(size_t)TS * NN * G1];
__device__ float g_h1[NN * HD], g_c1[NN * HD];
__device__ float g_h2[NN * KSZ], g_c2[NN * KSZ];
__device__ float g_ctx[NN * VSZ];
__device__ float g_partA[4 * NN * G1];              // LSTM1 k-split partials
__device__ float g_partC[16 * NN * G2];             // LSTM2 k-split partials
__device__ __nv_bfloat16 g_W1hi[(size_t)G1 * K1];   // [ctx|h1] recurrent weight hi/lo
__device__ __nv_bfloat16 g_W1lo[(size_t)G1 * K1];
__device__ __nv_bfloat16 g_W1ehi[(size_t)G1 * HD];  // emb-part weight hi/lo
__device__ __nv_bfloat16 g_W1elo[(size_t)G1 * HD];
__device__ __nv_bfloat16 g_Ehi[(size_t)VOC * HD];   // embedding table hi/lo
__device__ __nv_bfloat16 g_Elo[(size_t)VOC * HD];
__device__ __nv_bfloat16 g_Whi[(size_t)VOC * KOUT];
__device__ __nv_bfloat16 g_Wlo[(size_t)VOC * KOUT];
__device__ __nv_bfloat16 g_Xhi[(size_t)NROW * KOUT];
__device__ __nv_bfloat16 g_Xlo[(size_t)NROW * KOUT];

__device__ unsigned g_bar_count;
__device__ volatile unsigned g_bar_gen;

__device__ __forceinline__ float sigf(float x) { return 1.0f / (1.0f + expf(-x)); }

__device__ __forceinline__ uint32_t smem_u32(const void* p) {
    uint32_t a;
    asm("{ .reg .u64 t; cvta.to.shared.u64 t, %1; cvt.u32.u64 %0, t; }" : "=r"(a) : "l"(p));
    return a;
}
__device__ __forceinline__ void ldsm_x4(uint32_t* r, uint32_t addr) {
    asm volatile("ldmatrix.sync.aligned.m8n8.x4.shared.b16 {%0,%1,%2,%3}, [%4];"
                 : "=r"(r[0]), "=r"(r[1]), "=r"(r[2]), "=r"(r[3]) : "r"(addr));
}
__device__ __forceinline__ void mma_bf16(float* d, const uint32_t* a, const uint32_t* b) {
    asm volatile("mma.sync.aligned.m16n8k16.row.col.f32.bf16.bf16.f32 "
        "{%0,%1,%2,%3}, {%4,%5,%6,%7}, {%8,%9}, {%0,%1,%2,%3};"
        : "+f"(d[0]), "+f"(d[1]), "+f"(d[2]), "+f"(d[3])
        : "r"(a[0]), "r"(a[1]), "r"(a[2]), "r"(a[3]), "r"(b[0]), "r"(b[1]));
}
__device__ __forceinline__ void cp_async16(uint32_t dst, const void* src, bool pred) {
    int sz = pred ? 16 : 0;
    asm volatile("cp.async.cg.shared.global [%0], [%1], 16, %2;"
                 :: "r"(dst), "l"(src), "r"(sz) : "memory");
}
#define CP_COMMIT() asm volatile("cp.async.commit_group;" ::: "memory")
#define CP_WAIT(n)  asm volatile("cp.async.wait_group %0;" :: "n"(n) : "memory")

// swizzled SMEM offset within a [rows x 64B] bf16 k32 tile (ldmatrix conflict-free)
__device__ __forceinline__ uint32_t swz(int row, int c16) {
    return (uint32_t)(row * 64 + ((c16 ^ ((row >> 1) & 3)) << 4));
}

// ---------------- init ----------------
__global__ void init_kernel() {
    int i = blockIdx.x * blockDim.x + threadIdx.x;
    if (i == 0) { g_bar_count = 0; g_bar_gen = 0; }
    if (i < NN * HD)  { g_h1[i] = 0.f; g_c1[i] = 0.f; }
    if (i < NN * KSZ) { g_h2[i] = 0.f; g_c2[i] = 0.f; g_ctx[i] = 0.f; }
}

// ---------------- fused conversions (identical math to R9's 4 kernels) ----------------
__global__ void conv_all_kernel(
    const float* __restrict__ Wout, const float* __restrict__ Wih1,
    const float* __restrict__ Whh1, const float* __restrict__ emb)
{
    size_t i = (size_t)blockIdx.x * 256 + threadIdx.x;   // spans VOC*HD (largest)

    // embedding table (VOC*HD)
    {
        float w = emb[i];
        __nv_bfloat16 hi = __float2bfloat16(w);
        g_Ehi[i] = hi;
        g_Elo[i] = __float2bfloat16(w - __bfloat162float(hi));
    }
    // output projection weight (VOC*KOUT)
    if (i < (size_t)VOC * KOUT) {
        float w = Wout[i];
        __nv_bfloat16 hi = __float2bfloat16(w);
        g_Whi[i] = hi;
        g_Wlo[i] = __float2bfloat16(w - __bfloat162float(hi));
    }
    // recurrent W1 = [Wih1_ctx | Whh1]  (G1*K1)
    if (i < (size_t)G1 * K1) {
        int col = (int)(i / K1), k = (int)(i % K1);
        float w = (k < 128) ? Wih1[(size_t)col * 640 + 512 + k] : Whh1[(size_t)col * 512 + k - 128];
        __nv_bfloat16 hi = __float2bfloat16(w);
        g_W1hi[i] = hi;
        g_W1lo[i] = __float2bfloat16(w - __bfloat162float(hi));
    }
    // emb-part of Wih1 (G1*HD)
    if (i < (size_t)G1 * HD) {
        int col = (int)(i / HD), k = (int)(i % HD);
        float w = Wih1[(size_t)col * 640 + k];
        __nv_bfloat16 hi = __float2bfloat16(w);
        g_W1ehi[i] = hi;
        g_W1elo[i] = __float2bfloat16(w - __bfloat162float(hi));
    }
}

// ============================================================================
// pre1 via warp MMA (exact R9 version)
// ============================================================================
#define TILE_B 8192
#define STAGE_B (4 * TILE_B)
#define OUT_SMEM (2 * STAGE_B)

__global__ __launch_bounds__(256) void pre1_mma(
    const int* __restrict__ text,
    const float* __restrict__ bih1, const float* __restrict__ bhh1)
{
    extern __shared__ __align__(16) uint8_t sm[];
    uint32_t sbase = smem_u32(sm);

    int cb = blockIdx.x * 128;
    int mb = blockIdx.y * 128;
    int tx = threadIdx.x, wid = tx >> 5, lane = tx & 31;
    int wr = wid >> 2, wcid = wid & 3;

    float acc[4][4][4];
#pragma unroll
    for (int a = 0; a < 4; a++)
#pragma unroll
        for (int b = 0; b < 4; b++)
#pragma unroll
            for (int c = 0; c < 4; c++) acc[a][b][c] = 0.f;

    int lrow = tx >> 1;
    int cpair = (tx & 1) * 2;
    int gr0 = mb + lrow;
    bool xok = gr0 < NROW;
    int tok = 0;
    if (xok) {
        int tt = gr0 >> 6, nn = gr0 & 63;
        tok = text[nn * TDEC + tt];
    }
    const uint8_t* gXhi = (const uint8_t*)(g_Ehi + (size_t)tok * HD);
    const uint8_t* gXlo = (const uint8_t*)(g_Elo + (size_t)tok * HD);
    const uint8_t* gWhi = (const uint8_t*)(g_W1ehi + (size_t)(cb + lrow) * HD);
    const uint8_t* gWlo = (const uint8_t*)(g_W1elo + (size_t)(cb + lrow) * HD);

    int rA = (lane & 7) + ((lane & 8) ? 8 : 0);
    int cAq = lane >> 4;
    int rB = (lane & 7) + ((lane & 16) ? 8 : 0);
    int cBq = (lane >> 3) & 1;

    auto load_stage = [&](int kc, int stg) {
        uint32_t st = sbase + stg * STAGE_B;
        int kb = kc * 64;
#pragma unroll
        for (int q = 0; q < 2; q++) {
            int c = cpair + q;
            uint32_t so = swz(lrow, c);
            int go = kb + c * 16;
            cp_async16(st + so,              gXhi + go, xok);
            cp_async16(st + TILE_B + so,     gXlo + go, xok);
            cp_async16(st + 2 * TILE_B + so, gWhi + go, true);
            cp_async16(st + 3 * TILE_B + so, gWlo + go, true);
        }
        CP_COMMIT();
    };

    load_stage(0, 0);

    for (int kc = 0; kc < 16; kc++) {
        int stg = kc & 1;
        if (kc + 1 < 16) {
            load_stage(kc + 1, stg ^ 1);
            CP_WAIT(1);
        } else {
            CP_WAIT(0);
        }
        __syncthreads();

        uint32_t pXhi = sbase + stg * STAGE_B;
        uint32_t pXlo = pXhi + TILE_B;
        uint32_t pWhi = pXhi + 2 * TILE_B;
        uint32_t pWlo = pXhi + 3 * TILE_B;

#pragma unroll
        for (int ks = 0; ks < 2; ks++) {
            int c0 = ks * 2;
            uint32_t bh[8], bl[8];
#pragma unroll
            for (int pr = 0; pr < 2; pr++) {
                int n0 = wcid * 32 + pr * 16;
                ldsm_x4(bh + pr * 4, pWhi + swz(n0 + rB, c0 + cBq));
                ldsm_x4(bl + pr * 4, pWlo + swz(n0 + rB, c0 + cBq));
            }
#pragma unroll
            for (int mt = 0; mt < 4; mt++) {
                int m0 = wr * 64 + mt * 16;
                uint32_t ah[4], al[4];
                ldsm_x4(ah, pXhi + swz(m0 + rA, c0 + cAq));
                ldsm_x4(al, pXlo + swz(m0 + rA, c0 + cAq));
#pragma unroll
                for (int nt = 0; nt < 4; nt++) {
                    mma_bf16(acc[mt][nt], ah, &bh[nt * 2]);
                    mma_bf16(acc[mt][nt], ah, &bl[nt * 2]);
                    mma_bf16(acc[mt][nt], al, &bh[nt * 2]);
                }
            }
        }
        __syncthreads();
    }

    int g = lane >> 2, tg = lane & 3;
#pragma unroll
    for (int mt = 0; mt < 4; mt++) {
        int r0 = mb + wr * 64 + mt * 16 + g;
#pragma unroll
        for (int half = 0; half < 2; half++) {
            int gr = r0 + half * 8;
            if (gr >= NROW) continue;
            float* prow = g_pre1 + (size_t)gr * G1;
#pragma unroll
            for (int nt = 0; nt < 4; nt++) {
                int c = cb + wcid * 32 + nt * 8 + 2 * tg;
                float2 o;
                o.x = acc[mt][nt][half * 2 + 0] + bih1[c] + bhh1[c];
                o.y = acc[mt][nt][half * 2 + 1] + bih1[c + 1] + bhh1[c + 1];
                *(float2*)(prow + c) = o;
            }
        }
    }
}

// ============================================================================
// Persistent recurrence (exact R9 version — known 4222us config)
// ============================================================================
#define AW_HI 0
#define AW_LO 20480
#define AX_HI 40960
#define AX_LO 61440
#define A_SMEM 81920

__device__ __forceinline__ void gbar(unsigned* gen) {
    __syncthreads();
    if (threadIdx.x == 0) {
        unsigned g = ++(*gen);
        __threadfence();
        unsigned arr = atomicAdd(&g_bar_count, 1u) + 1u;
        if (arr == g * NBLK) {
            g_bar_gen = g;
        } else {
            while (g_bar_gen < g) __nanosleep(64);
        }
        __threadfence();
    }
    __syncthreads();
}

__global__ __launch_bounds__(512) void loop_kernel(
    const float* __restrict__ enc_key, const float* __restrict__ values,
    const int* __restrict__ lens,
    const float* __restrict__ Wih2, const float* __restrict__ Whh2,
    const float* __restrict__ bih2, const float* __restrict__ bhh2,
    float* __restrict__ out_attn)
{
    extern __shared__ __align__(16) uint8_t dsm[];
    uint32_t sA = smem_u32(dsm);

    int bid = blockIdx.x;
    int tx = threadIdx.x;
    int lane = tx & 31, warp = tx >> 5;
    unsigned gen = 0;

    __shared__ float sXC[64][9];
    __shared__ float sWC[8][64];
    __shared__ __align__(16) float sh2[128];
    __shared__ float se[512];
    __shared__ float sbuf[512];
    __shared__ float swred[32];

    int acg = bid >> 2;
    int aky = bid & 3;
    int wr   = warp >> 2;
    int wcid = warp & 3;
    int rA = (lane & 7) + ((lane & 8) ? 8 : 0);
    int cAq = lane >> 4;
    int rB = (lane & 7) + ((lane & 16) ? 8 : 0);
    int cBq = (lane >> 3) & 1;

    int ccg = bid & 7;
    int cky = bid >> 3;
    int cxrow = tx >> 3;
    int cxk   = tx & 7;
    int cwk   = tx >> 6;
    int cwc   = tx & 63;
    int grWC = (cwc >> 4) * 128 + ccg * 16 + (cwc & 15);
    const float* wihC = Wih2 + (size_t)grWC * 512;
    const float* whhC = Whh2 + (size_t)grWC * 128;

    int lenD = (bid < NN) ? lens[bid] : 0;

    // preload resident W1 slice (64 cols x 160 k, hi+lo)
    for (int i = tx; i < 64 * 5 * 4; i += 512) {
        int r = i / 20, rem = i % 20, kc = rem >> 2, c16 = rem & 3;
        size_t go = (size_t)(acg * 64 + r) * K1 + aky * 160 + kc * 32 + c16 * 8;
        uint32_t so = (uint32_t)(kc * 4096) + swz(r, c16);
        *(uint4*)(dsm + AW_HI + so) = *(const uint4*)(g_W1hi + go);
        *(uint4*)(dsm + AW_LO + so) = *(const uint4*)(g_W1lo + go);
    }
    __syncthreads();

    for (int t = 0; t < TS; t++) {
        // Phase A: HMMA
        {
            for (int i = tx; i < 64 * 160; i += 512) {
                int r = i / 160, kl = i % 160;
                int kg = aky * 160 + kl;
                float v = (kg < 128) ? __ldcg(&g_ctx[r * VSZ + kg])
                                     : __ldcg(&g_h1[r * HD + kg - 128]);
                __nv_bfloat16 hi = __float2bfloat16(v);
                __nv_bfloat16 lo = __float2bfloat16(v - __bfloat162float(hi));
                uint32_t off = (uint32_t)((kl >> 5) * 4096) + swz(r, (kl & 31) >> 3) + (kl & 7) * 2;
                *(__nv_bfloat16*)(dsm + AX_HI + off) = hi;
                *(__nv_bfloat16*)(dsm + AX_LO + off) = lo;
            }
            __syncthreads();

            float acc2[2][4];
#pragma unroll
            for (int a = 0; a < 2; a++)
#pragma unroll
                for (int c = 0; c < 4; c++) acc2[a][c] = 0.f;

#pragma unroll
            for (int kc = 0; kc < 5; kc++) {
                uint32_t tW = sA + kc * 4096;
                uint32_t tX = sA + AX_HI + kc * 4096;
#pragma unroll
                for (int ks = 0; ks < 2; ks++) {
                    int c0 = ks * 2;
                    uint32_t bh[4], bl[4], ah[4], al[4];
                    ldsm_x4(bh, tW + AW_HI + swz(wcid * 16 + rB, c0 + cBq));
                    ldsm_x4(bl, tW + AW_LO + swz(wcid * 16 + rB, c0 + cBq));
                    ldsm_x4(ah, tX + swz(wr * 16 + rA, c0 + cAq));
                    ldsm_x4(al, tX + (AX_LO - AX_HI) + swz(wr * 16 + rA, c0 + cAq));
#pragma unroll
                    for (int nt = 0; nt < 2; nt++) {
                        mma_bf16(acc2[nt], ah, &bh[nt * 2]);
                        mma_bf16(acc2[nt], ah, &bl[nt * 2]);
                        mma_bf16(acc2[nt], al, &bh[nt * 2]);
                    }
                }
            }
            int g = lane >> 2, tg = lane & 3;
#pragma unroll
            for (int half = 0; half < 2; half++) {
                int n = wr * 16 + g + half * 8;
#pragma unroll
                for (int nt = 0; nt < 2; nt++) {
                    int gcol = acg * 64 + wcid * 16 + nt * 8 + 2 * tg;
                    float2 o;
                    o.x = acc2[nt][half * 2 + 0];
                    o.y = acc2[nt][half * 2 + 1];
                    *(float2*)&g_partA[((size_t)aky * NN + n) * G1 + gcol] = o;
                }
            }
        }
        gbar(&gen);

        // Phase B
        if (bid < 64) {
            int idx = bid * 512 + tx;
            int n = idx >> 9, k = idx & 511;
            const float* gp = g_pre1 + ((size_t)t * NN + n) * G1;
            float gi = gp[k], gf = gp[512 + k], gg = gp[1024 + k], go = gp[1536 + k];
#pragma unroll
            for (int ky = 0; ky < 4; ky++) {
                const float* pp = g_partA + ((size_t)ky * NN + n) * G1;
                gi += __ldcg(pp + k);
                gf += __ldcg(pp + 512 + k);
                gg += __ldcg(pp + 1024 + k);
                go += __ldcg(pp + 1536 + k);
            }
            float c = sigf(gf) * g_c1[idx] + sigf(gi) * tanhf(gg);
            g_c1[idx] = c;
            __stcg(&g_h1[idx], sigf(go) * tanhf(c));
        }
        gbar(&gen);

        // Phase C
        {
            float acc[4][2];
#pragma unroll
            for (int i = 0; i < 4; i++) { acc[i][0] = 0.f; acc[i][1] = 0.f; }

            for (int k0 = 0; k0 < 40; k0 += 8) {
                int kbase = cky * 40 + k0;
                {
                    int kg = kbase + cxk;
                    sXC[cxrow][cxk] = (kg < 512) ? __ldcg(&g_h1[cxrow * HD + kg])
                                                 : __ldcg(&g_h2[cxrow * KSZ + kg - 512]);
                    int kg2 = kbase + cwk;
                    sWC[cwk][cwc] = (kg2 < 512) ? wihC[kg2] : whhC[kg2 - 512];
                }
                __syncthreads();
#pragma unroll
                for (int kk = 0; kk < 8; kk++) {
                    float wv0 = sWC[kk][lane & 31];
                    float wv1 = sWC[kk][(lane & 31) + 32];
#pragma unroll
                    for (int i = 0; i < 4; i++) {
                        float xv = sXC[warp * 4 + i][kk];
                        acc[i][0] += xv * wv0;
                        acc[i][1] += xv * wv1;
                    }
                }
                __syncthreads();
            }
#pragma unroll
            for (int j = 0; j < 2; j++) {
                int cc = lane + 32 * j;
                int gcol = (cc >> 4) * 128 + ccg * 16 + (cc & 15);
#pragma unroll
                for (int i = 0; i < 4; i++) {
                    int n = warp * 4 + i;
                    g_partC[((size_t)cky * NN + n) * G2 + gcol] = acc[i][j];
                }
            }
        }
        gbar(&gen);

        // Phase D
        if (bid < NN) {
            int n = bid;
            {
                float v = bih2[tx] + bhh2[tx];
#pragma unroll
                for (int ky = 0; ky < 16; ky++)
                    v += __ldcg(&g_partC[((size_t)ky * NN + n) * G2 + tx]);
                sbuf[tx] = v;
            }
            __syncthreads();
            if (tx < 128) {
                float gi = sbuf[tx], gf = sbuf[128 + tx], gg = sbuf[256 + tx], go = sbuf[384 + tx];
                float c = sigf(gf) * g_c2[n * KSZ + tx] + sigf(gi) * tanhf(gg);
                g_c2[n * KSZ + tx] = c;
                float h = sigf(go) * tanhf(c);
                __stcg(&g_h2[n * KSZ + tx], h);
                sh2[tx] = h;
                size_t xr = ((size_t)t * NN + n) * KOUT + tx;
                __nv_bfloat16 hi = __float2bfloat16(h);
                g_Xhi[xr] = hi;
                g_Xlo[xr] = __float2bfloat16(h - __bfloat162float(hi));
            }
            __syncthreads();

            float e;
            {
                const float4* er = (const float4*)(enc_key + ((size_t)n * TEN + tx) * KSZ);
                const float4* h4 = (const float4*)sh2;
                e = 0.f;
#pragma unroll
                for (int q = 0; q < 32; q++) {
                    float4 a = er[q], b = h4[q];
                    e += a.x * b.x + a.y * b.y + a.z * b.z + a.w * b.w;
                }
            }
            float m = e;
#pragma unroll
            for (int s = 16; s > 0; s >>= 1) m = fmaxf(m, __shfl_xor_sync(0xffffffffu, m, s));
            if (lane == 0) swred[warp] = m;
            __syncthreads();
            if (tx < 32) {
                float mm = (tx < 16) ? swred[tx] : -1e30f;
#pragma unroll
                for (int s = 8; s > 0; s >>= 1) mm = fmaxf(mm, __shfl_xor_sync(0xffffffffu, mm, s));
                if (tx == 0) swred[0] = mm;
            }
            __syncthreads();
            float M = swred[0];

            float p = (tx < lenD) ? expf(e - M) : 0.f;
            float sum = p;
#pragma unroll
            for (int s = 16; s > 0; s >>= 1) sum += __shfl_xor_sync(0xffffffffu, sum, s);
            __syncthreads();
            if (lane == 0) swred[warp] = sum;
            __syncthreads();
            if (tx < 32) {
                float ss = (tx < 16) ? swred[tx] : 0.f;
#pragma unroll
                for (int s = 8; s > 0; s >>= 1) ss += __shfl_xor_sync(0xffffffffu, ss, s);
                if (tx == 0) swred[0] = ss;
            }
            __syncthreads();
            float a = p * (1.f / swred[0]);
            se[tx] = a;
            out_attn[((size_t)n * TS + t) * TEN + tx] = a;
            __syncthreads();

            int v = tx & 127, qq = tx >> 7;
            float accv = 0.f;
            const float* vb = values + ((size_t)n * TEN + qq * 128) * VSZ + v;
#pragma unroll 8
            for (int it = 0; it < 128; it++) accv += se[qq * 128 + it] * vb[it * VSZ];
            sbuf[tx] = accv;
            __syncthreads();
            if (tx < 128) {
                float cv = sbuf[tx] + sbuf[128 + tx] + sbuf[256 + tx] + sbuf[384 + tx];
                __stcg(&g_ctx[n * VSZ + tx], cv);
                size_t xr = ((size_t)t * NN + n) * KOUT + 128 + tx;
                __nv_bfloat16 hi = __float2bfloat16(cv);
                g_Xhi[xr] = hi;
                g_Xlo[xr] = __float2bfloat16(cv - __bfloat162float(hi));
            }
        }
        gbar(&gen);
    }
}

// ============================================================================
// Output projection via warp MMA, cp.async 2-stage pipeline (exact R9 version).
// ============================================================================
__global__ __launch_bounds__(256) void out_gemm_mma(
    const float* __restrict__ bout, float* __restrict__ pred)
{
    extern __shared__ __align__(16) uint8_t sm[];
    uint32_t sbase = smem_u32(sm);

    int cb = blockIdx.x * 128;
    int mb = blockIdx.y * 128;
    int tx = threadIdx.x, wid = tx >> 5, lane = tx & 31;
    int wr = wid >> 2, wcid = wid & 3;

    float acc[4][4][4];
#pragma unroll
    for (int a = 0; a < 4; a++)
#pragma unroll
        for (int b = 0; b < 4; b++)
#pragma unroll
            for (int c = 0; c < 4; c++) acc[a][b][c] = 0.f;

    int lrow = tx >> 1;
    int cpair = (tx & 1) * 2;
    bool xok = (mb + lrow) < NROW;
    const uint8_t* gXhi = (const uint8_t*)(g_Xhi + (size_t)(mb + lrow) * KOUT);
    const uint8_t* gXlo = (const uint8_t*)(g_Xlo + (size_t)(mb + lrow) * KOUT);
    const uint8_t* gWhi = (const uint8_t*)(g_Whi + (size_t)(cb + lrow) * KOUT);
    const uint8_t* gWlo = (const uint8_t*)(g_Wlo + (size_t)(cb + lrow) * KOUT);

    int rA = (lane & 7) + ((lane & 8) ? 8 : 0);
    int cAq = lane >> 4;
    int rB = (lane & 7) + ((lane & 16) ? 8 : 0);
    int cBq = (lane >> 3) & 1;

    auto load_stage = [&](int kc, int stg) {
        uint32_t st = sbase + stg * STAGE_B;
        int kb = kc * 64;
#pragma unroll
        for (int q = 0; q < 2; q++) {
            int c = cpair + q;
            uint32_t so = swz(lrow, c);
            int go = kb + c * 16;
            cp_async16(st + so,              gXhi + go, xok);
            cp_async16(st + TILE_B + so,     gXlo + go, xok);
            cp_async16(st + 2 * TILE_B + so, gWhi + go, true);
            cp_async16(st + 3 * TILE_B + so, gWlo + go, true);
        }
        CP_COMMIT();
    };

    load_stage(0, 0);

    for (int kc = 0; kc < 8; kc++) {
        int stg = kc & 1;
        if (kc + 1 < 8) {
            load_stage(kc + 1, stg ^ 1);
            CP_WAIT(1);
        } else {
            CP_WAIT(0);
        }
        __syncthreads();

        uint32_t pXhi = sbase + stg * STAGE_B;
        uint32_t pXlo = pXhi + TILE_B;
        uint32_t pWhi = pXhi + 2 * TILE_B;
        uint32_t pWlo = pXhi + 3 * TILE_B;

#pragma unroll
        for (int ks = 0; ks < 2; ks++) {
            int c0 = ks * 2;
            uint32_t bh[8], bl[8];
#pragma unroll
            for (int pr = 0; pr < 2; pr++) {
                int n0 = wcid * 32 + pr * 16;
                ldsm_x4(bh + pr * 4, pWhi + swz(n0 + rB, c0 + cBq));
                ldsm_x4(bl + pr * 4, pWlo + swz(n0 + rB, c0 + cBq));
            }
#pragma unroll
            for (int mt = 0; mt < 4; mt++) {
                int m0 = wr * 64 + mt * 16;
                uint32_t ah[4], al[4];
                ldsm_x4(ah, pXhi + swz(m0 + rA, c0 + cAq));
                ldsm_x4(al, pXlo + swz(m0 + rA, c0 + cAq));
#pragma unroll
                for (int nt = 0; nt < 4; nt++) {
                    mma_bf16(acc[mt][nt], ah, &bh[nt * 2]);
                    mma_bf16(acc[mt][nt], ah, &bl[nt * 2]);
                    mma_bf16(acc[mt][nt], al, &bh[nt * 2]);
                }
            }
        }
        __syncthreads();
    }

    int g = lane >> 2, tg = lane & 3;
#pragma unroll
    for (int mt = 0; mt < 4; mt++) {
        int r0 = mb + wr * 64 + mt * 16 + g;
#pragma unroll
        for (int half = 0; half < 2; half++) {
            int gr = r0 + half * 8;
            if (gr >= NROW) continue;
            int t = gr >> 6, n = gr & 63;
            float* prow = pred + (size_t)n * ((size_t)TS * VOC) + (size_t)t * VOC;
#pragma unroll
            for (int nt = 0; nt < 4; nt++) {
                int c = cb + wcid * 32 + nt * 8 + 2 * tg;
                float2 o;
                o.x = acc[mt][nt][half * 2 + 0] + bout[c];
                o.y = acc[mt][nt][half * 2 + 1] + bout[c + 1];
                *(float2*)(prow + c) = o;
            }
        }
    }
}

// ---------------- launch ----------------
extern "C" void kernel_launch(void* const* d_in, const int* in_sizes, int n_in,
                              void* d_out, int out_size)
{
    const float* enc_key = (const float*)d_in[0];
    const float* values  = (const float*)d_in[1];
    const int*   lens    = (const int*)d_in[2];
    const int*   text    = (const int*)d_in[3];
    const float* emb     = (const float*)d_in[4];
    const float* Wih1    = (const float*)d_in[5];
    const float* Whh1    = (const float*)d_in[6];
    const float* bih1    = (const float*)d_in[7];
    const float* bhh1    = (const float*)d_in[8];
    const float* Wih2    = (const float*)d_in[9];
    const float* Whh2    = (const float*)d_in[10];
    const float* bih2    = (const float*)d_in[11];
    const float* bhh2    = (const float*)d_in[12];
    const float* Wout    = (const float*)d_in[13];
    const float* bout    = (const float*)d_in[14];

    float* pred = (float*)d_out;
    float* attn = (float*)d_out + (size_t)NN * TS * VOC;

    cudaFuncSetAttribute(out_gemm_mma, cudaFuncAttributeMaxDynamicSharedMemorySize, OUT_SMEM);
    cudaFuncSetAttribute(pre1_mma, cudaFuncAttributeMaxDynamicSharedMemorySize, OUT_SMEM);
    cudaFuncSetAttribute(loop_kernel, cudaFuncAttributeMaxDynamicSharedMemorySize, A_SMEM);

    init_kernel<<<128, 256>>>();
    conv_all_kernel<<<(VOC * HD) / 256, 256>>>(Wout, Wih1, Whh1, emb);
    pre1_mma<<<dim3(16, 50), 256, OUT_SMEM>>>(text, bih1, bhh1);
    loop_kernel<<<NBLK, 512, A_SMEM>>>(enc_key, values, lens,
                                       Wih2, Whh2, bih2, bhh2, attn);
    out_gemm_mma<<<dim3(250, 50), 256, OUT_SMEM>>>(bout, pred);
}